// round 2
// baseline (speedup 1.0000x reference)
#include <cuda_runtime.h>
#include <math.h>

// ---------------------------------------------------------------------------
// WMVLoss: scores = sigmoid(x1 - x0); loss = sum over (neg i, pos j) of
// max(gamma - (s_j - s_i), 0)^2 / N   (P=2, gamma=0.3)
//
// NOTE: reference declares target as int64 but JAX default (x64 disabled)
// downcasts to int32 -> read as const int*.
// ---------------------------------------------------------------------------

#define MAXN 32768
#define TILE 2048
#define BLK  256

__device__ float  g_pos[MAXN];
__device__ float  g_neg[MAXN];
__device__ int    g_pos_cnt;
__device__ int    g_neg_cnt;
__device__ double g_sum;

__global__ void wmv_init_kernel() {
    g_pos_cnt = 0;
    g_neg_cnt = 0;
    g_sum     = 0.0;
}

__global__ void wmv_score_kernel(const float* __restrict__ x,
                                 const int* __restrict__ tgt, int n) {
    int i = blockIdx.x * blockDim.x + threadIdx.x;
    if (i >= n) return;
    float x0 = x[2 * i + 0];
    float x1 = x[2 * i + 1];
    // softmax(.,axis=-1)[:,1] for 2 classes == sigmoid(x1 - x0)
    float s = 1.0f / (1.0f + expf(x0 - x1));
    if (tgt[i] == 1) {
        int k = atomicAdd(&g_pos_cnt, 1);
        g_pos[k] = s;
    } else {
        int k = atomicAdd(&g_neg_cnt, 1);
        g_neg[k] = s;
    }
}

__global__ void __launch_bounds__(BLK)
wmv_pair_kernel(float gamma) {
    __shared__ float sp[TILE];
    __shared__ double warp_part[BLK / 32];

    const int pos_cnt = g_pos_cnt;
    const int neg_cnt = g_neg_cnt;

    // Load this block's tile of positive scores; pad with +huge so that
    // c - pad is hugely negative -> fmaxf(...,0)=0 -> contributes nothing.
    const int base = blockIdx.y * TILE;
    for (int t = threadIdx.x; t < TILE; t += BLK) {
        int j = base + t;
        sp[t] = (j < pos_cnt) ? g_pos[j] : 3.0e37f;
    }
    __syncthreads();

    const int i = blockIdx.x * BLK + threadIdx.x;
    // Invalid negatives get c = -huge: c - s_j is hugely negative -> 0.
    const float c = (i < neg_cnt) ? (gamma + g_neg[i]) : -3.0e37f;

    float a0 = 0.f, a1 = 0.f, a2 = 0.f, a3 = 0.f;
    const float4* sp4 = (const float4*)sp;
#pragma unroll 8
    for (int k = 0; k < TILE / 4; k++) {
        float4 v = sp4[k];                 // broadcast LDS.128 across warp
        float m0 = fmaxf(c - v.x, 0.f);
        float m1 = fmaxf(c - v.y, 0.f);
        float m2 = fmaxf(c - v.z, 0.f);
        float m3 = fmaxf(c - v.w, 0.f);
        a0 = fmaf(m0, m0, a0);
        a1 = fmaf(m1, m1, a1);
        a2 = fmaf(m2, m2, a2);
        a3 = fmaf(m3, m3, a3);
    }
    float acc = (a0 + a1) + (a2 + a3);

    // Warp reduce (fp32), then block reduce in double, one atomic per block.
    for (int off = 16; off > 0; off >>= 1)
        acc += __shfl_down_sync(0xFFFFFFFFu, acc, off);

    const int lane = threadIdx.x & 31;
    const int wid  = threadIdx.x >> 5;
    if (lane == 0) warp_part[wid] = (double)acc;
    __syncthreads();

    if (wid == 0) {
        double v = (lane < BLK / 32) ? warp_part[lane] : 0.0;
        for (int off = 16; off > 0; off >>= 1)
            v += __shfl_down_sync(0xFFFFFFFFu, v, off);
        if (lane == 0) atomicAdd(&g_sum, v);
    }
}

__global__ void wmv_final_kernel(float* __restrict__ out, int n) {
    out[0] = (float)(g_sum / (double)n);
}

extern "C" void kernel_launch(void* const* d_in, const int* in_sizes, int n_in,
                              void* d_out, int out_size) {
    const float* x   = (const float*)d_in[0];   // [N,2] f32
    const int*   tgt = (const int*)d_in[1];     // [N] int32 (JAX x64 off)
    float*       out = (float*)d_out;
    const int n = in_sizes[1];                  // N (target count)

    wmv_init_kernel<<<1, 1>>>();
    wmv_score_kernel<<<(n + BLK - 1) / BLK, BLK>>>(x, tgt, n);

    dim3 grid((n + BLK - 1) / BLK, (n + TILE - 1) / TILE);
    wmv_pair_kernel<<<grid, BLK>>>(0.3f);

    wmv_final_kernel<<<1, 1>>>(out, n);
}